// round 11
// baseline (speedup 1.0000x reference)
#include <cuda_runtime.h>
#include <cstddef>

#define NIMG 8192
#define GFC 64
#define NBLK_FC 128                /* 128*64 = 8192 exact */

// act hi/lo (tf32 split), [img][400]
__device__ __align__(16) float g_act_hi[(size_t)NIMG * 400];
__device__ __align__(16) float g_act_lo[(size_t)NIMG * 400];
// w1 hi/lo, padded to 128 outputs, [o][400]
__device__ __align__(16) float g_w1_hi[128 * 400];
__device__ __align__(16) float g_w1_lo[128 * 400];

__device__ __forceinline__ void tf32_split(float v, float& hf, float& lf) {
    unsigned hi, lo;
    asm("cvt.rna.tf32.f32 %0, %1;" : "=r"(hi) : "f"(v));
    hf = __uint_as_float(hi);
    float r = v - hf;
    asm("cvt.rna.tf32.f32 %0, %1;" : "=r"(lo) : "f"(r));
    lf = __uint_as_float(lo);
}

__device__ __forceinline__ void mma8(float* c, unsigned a0, unsigned a1,
                                     unsigned a2, unsigned a3,
                                     unsigned b0, unsigned b1) {
    asm("mma.sync.aligned.m16n8k8.row.col.f32.tf32.tf32.f32 "
        "{%0,%1,%2,%3},{%4,%5,%6,%7},{%8,%9},{%0,%1,%2,%3};"
        : "+f"(c[0]), "+f"(c[1]), "+f"(c[2]), "+f"(c[3])
        : "r"(a0), "r"(a1), "r"(a2), "r"(a3), "r"(b0), "r"(b1));
}

// ---------------------------------------------------------------------------
// Prep: split fw1 into tf32 hi/lo, pad outputs 120->128 with zeros.
// ---------------------------------------------------------------------------
__global__ void prep_kernel(const float* __restrict__ fw1)
{
    int i = blockIdx.x * 256 + threadIdx.x;
    if (i >= 128 * 400) return;
    int o = i / 400, k = i % 400;
    float v = (o < 120) ? fw1[o * 400 + k] : 0.f;
    float hf, lf;
    tf32_split(v, hf, lf);
    g_w1_hi[i] = hf;
    g_w1_lo[i] = lf;
}

// ---------------------------------------------------------------------------
// Kernel 1: fused conv1->relu->pool1->conv2->relu->pool2, warp-per-image.
// Epilogue writes tf32 hi/lo act rows [img][400], coalesced per warp.
// ---------------------------------------------------------------------------
__global__ __launch_bounds__(256) void conv_kernel(const float* __restrict__ x,
                                                   const float* __restrict__ w1,
                                                   const float* __restrict__ w2)
{
    __shared__ __align__(16) float s_w1[456];
    __shared__ __align__(16) float s_w2[2400];
    __shared__ __align__(16) float s_A[8][768];
    __shared__ __align__(16) float s_B[8][880];
    __shared__ __align__(16) float s_po[8][400];

    const int tid  = threadIdx.x;
    const int wid  = tid >> 5;
    const int lane = tid & 31;
    const int img  = blockIdx.x * 8 + wid;

    for (int i = tid; i < 450; i += 256) s_w1[i] = w1[i];
    for (int i = tid; i < 2400; i += 256) s_w2[i] = w2[i];
    __syncthreads();

    float* A = s_A[wid];
    float* B = s_B[wid];

    const float* xb = x + (size_t)img * 3072;
    for (int i = lane; i < 768; i += 32) {
        int c  = i >> 8;
        int rr = (i >> 4) & 15;
        int cc = i & 15;
        A[i] = xb[c * 1024 + rr * 32 + cc];
    }
    __syncwarp();

    // conv1 + relu: 96 tasks, each 3x3 outputs
    #pragma unroll
    for (int pass = 0; pass < 3; pass++) {
        int u   = lane + pass * 32;
        int oc  = u >> 4;
        int rem = u & 15;
        int r0  = (rem >> 2) * 3;
        int c0  = (rem & 3) * 3;
        float acc[3][3];
        #pragma unroll
        for (int i = 0; i < 3; i++)
            #pragma unroll
            for (int j = 0; j < 3; j++) acc[i][j] = 0.f;

        for (int c = 0; c < 3; c++) {
            float wreg[25];
            const float* wb = &s_w1[(oc * 3 + c) * 25];
            #pragma unroll
            for (int i = 0; i < 25; i++) wreg[i] = wb[i];
            const float* Ac = &A[c * 256];
            #pragma unroll
            for (int rr = 0; rr < 7; rr++) {
                float p[7];
                const float* pr = &Ac[(r0 + rr) * 16 + c0];
                #pragma unroll
                for (int j = 0; j < 7; j++) p[j] = pr[j];
                #pragma unroll
                for (int orow = 0; orow < 3; orow++) {
                    int uu = rr - orow;
                    if (uu >= 0 && uu < 5) {
                        #pragma unroll
                        for (int v = 0; v < 5; v++) {
                            float w = wreg[uu * 5 + v];
                            #pragma unroll
                            for (int j = 0; j < 3; j++)
                                acc[orow][j] += p[v + j] * w;
                        }
                    }
                }
            }
        }
        #pragma unroll
        for (int orow = 0; orow < 3; orow++)
            #pragma unroll
            for (int j = 0; j < 3; j++)
                B[(oc * 12 + r0 + orow) * 12 + c0 + j] = fmaxf(acc[orow][j], 0.f);
    }
    __syncwarp();

    for (int t = lane; t < 600; t += 32) {
        int oc = t / 100;
        int rr = (t % 100) / 10;
        int cc = t % 10;
        const float* c1 = &B[(oc * 12 + rr) * 12 + cc];
        A[(oc * 10 + rr) * 12 + cc] = fmaxf(fmaxf(c1[0], c1[1]), fmaxf(c1[12], c1[13]));
    }
    __syncwarp();

    // conv2 + relu: 32 tasks = oc(16) x rowhalf(2)
    {
        int oc = lane >> 1;
        int r0 = (lane & 1) * 3;
        float acc[3][6];
        #pragma unroll
        for (int i = 0; i < 3; i++)
            #pragma unroll
            for (int j = 0; j < 6; j++) acc[i][j] = 0.f;

        for (int c = 0; c < 6; c++) {
            float wreg[25];
            const float* wb = &s_w2[(oc * 6 + c) * 25];
            #pragma unroll
            for (int i = 0; i < 25; i++) wreg[i] = wb[i];
            #pragma unroll
            for (int rr = 0; rr < 7; rr++) {
                const float* pr = &A[(c * 10 + r0 + rr) * 12];
                float p[10];
                float4 v0 = *reinterpret_cast<const float4*>(&pr[0]);
                float4 v1 = *reinterpret_cast<const float4*>(&pr[4]);
                p[0] = v0.x; p[1] = v0.y; p[2] = v0.z; p[3] = v0.w;
                p[4] = v1.x; p[5] = v1.y; p[6] = v1.z; p[7] = v1.w;
                p[8] = pr[8]; p[9] = pr[9];
                #pragma unroll
                for (int orow = 0; orow < 3; orow++) {
                    int uu = rr - orow;
                    if (uu >= 0 && uu < 5) {
                        #pragma unroll
                        for (int v = 0; v < 5; v++) {
                            float w = wreg[uu * 5 + v];
                            #pragma unroll
                            for (int j = 0; j < 6; j++)
                                acc[orow][j] += p[v + j] * w;
                        }
                    }
                }
            }
        }
        #pragma unroll
        for (int orow = 0; orow < 3; orow++)
            #pragma unroll
            for (int j = 0; j < 6; j++)
                B[(oc * 6 + r0 + orow) * 8 + j] = fmaxf(acc[orow][j], 0.f);
    }
    __syncwarp();

    // pool2 -> s_po[wid][k]
    for (int t = lane; t < 400; t += 32) {
        int oc = t / 25;
        int rr = (t % 25) / 5;
        int cc = t % 5;
        const float* c2 = &B[(oc * 6 + rr) * 8 + cc];
        s_po[wid][t] = fmaxf(fmaxf(c2[0], c2[1]), fmaxf(c2[8], c2[9]));
    }
    __syncwarp();

    // tf32 split + coalesced per-warp store of this image's 400-row
    float* dh = &g_act_hi[(size_t)img * 400];
    float* dl = &g_act_lo[(size_t)img * 400];
    for (int k = lane; k < 400; k += 32) {
        float hf, lf;
        tf32_split(s_po[wid][k], hf, lf);
        dh[k] = hf;
        dl[k] = lf;
    }
}

// ---------------------------------------------------------------------------
// Kernel 2: fc1 via mma.sync tf32 (3xTF32), fc2/fc3 scalar fp32.
// 128 blocks x 256 threads (8 warps); 64 images per block.
// K staged in 10 chunks of 40 (smem stride 44 = conflict-free frag loads).
// Warp w: M-tile = w>>1 (16 imgs), N-tiles = (w&1)*8 .. +7 (8 outs each).
// ---------------------------------------------------------------------------
#define KC 40
#define NCHK 10
#define SST 44

__global__ __launch_bounds__(256) void fc_kernel(const float* __restrict__ fb1,
                                                 const float* __restrict__ fw2,
                                                 const float* __restrict__ fb2,
                                                 const float* __restrict__ fw3,
                                                 const float* __restrict__ fb3,
                                                 float* __restrict__ out)
{
    extern __shared__ __align__(16) float sm[];
    float* s_a_hi = sm;                  // [64][44] = 2816
    float* s_a_lo = s_a_hi + 64 * SST;   // 2816
    float* s_w_hi = s_a_lo + 64 * SST;   // [128][44] = 5632
    float* s_w_lo = s_w_hi + 128 * SST;  // 5632
    float* s_h1T  = s_w_lo + 128 * SST;  // [120][64] = 7680
    float* s_w2T  = s_h1T + 120 * 64;    // [120][84] = 10080
    float* s_w3   = s_w2T + 120 * 84;    // 840
    float* s_b1   = s_w3 + 840;          // 120
    float* s_b2   = s_b1 + 120;          // 84
    float* s_b3   = s_b2 + 84;           // 12 (pad)
    float* s_h2   = sm;                  // alias after fc1: [64][84] = 5376

    const int tid  = threadIdx.x;
    const int lane = tid & 31;
    const int w    = tid >> 5;
    const int gid  = lane >> 2;
    const int tig  = lane & 3;
    const int img0 = blockIdx.x * GFC;

    // stage w2T [k][84], w3, biases (regions untouched by chunk staging)
    for (int i = tid; i < 120 * 84; i += 256) {
        int o = i / 120, k = i % 120;
        s_w2T[k * 84 + o] = fw2[i];
    }
    for (int i = tid; i < 840; i += 256) s_w3[i] = fw3[i];
    if (tid < 120) s_b1[tid] = fb1[tid];
    else if (tid < 204) s_b2[tid - 120] = fb2[tid - 120];
    else if (tid < 214) s_b3[tid - 204] = fb3[tid - 204];

    // ---- fc1 via MMA
    const int mt = w >> 1;          // 0..3
    const int nb = (w & 1) * 8;     // ntile base
    float c[8][4];
    #pragma unroll
    for (int i = 0; i < 8; i++)
        #pragma unroll
        for (int j = 0; j < 4; j++) c[i][j] = 0.f;

    for (int ch = 0; ch < NCHK; ch++) {
        const int kc = ch * KC;
        __syncthreads();
        // stage act chunk (hi+lo): 64 rows x 20 float2
        for (int j = tid; j < 64 * 20; j += 256) {
            int row = j / 20, col = (j % 20) * 2;
            size_t gi = (size_t)(img0 + row) * 400 + kc + col;
            *reinterpret_cast<float2*>(&s_a_hi[row * SST + col]) =
                *reinterpret_cast<const float2*>(&g_act_hi[gi]);
            *reinterpret_cast<float2*>(&s_a_lo[row * SST + col]) =
                *reinterpret_cast<const float2*>(&g_act_lo[gi]);
        }
        // stage w1 chunk (hi+lo): 128 rows x 20 float2
        for (int j = tid; j < 128 * 20; j += 256) {
            int row = j / 20, col = (j % 20) * 2;
            size_t gi = (size_t)row * 400 + kc + col;
            *reinterpret_cast<float2*>(&s_w_hi[row * SST + col]) =
                *reinterpret_cast<const float2*>(&g_w1_hi[gi]);
            *reinterpret_cast<float2*>(&s_w_lo[row * SST + col]) =
                *reinterpret_cast<const float2*>(&g_w1_lo[gi]);
        }
        __syncthreads();

        #pragma unroll
        for (int ks = 0; ks < KC / 8; ks++) {
            const int kb = ks * 8;
            const float* ah = &s_a_hi[(mt * 16 + gid) * SST + kb + tig];
            const float* al = &s_a_lo[(mt * 16 + gid) * SST + kb + tig];
            unsigned a0h = __float_as_uint(ah[0]);
            unsigned a1h = __float_as_uint(ah[8 * SST]);
            unsigned a2h = __float_as_uint(ah[4]);
            unsigned a3h = __float_as_uint(ah[8 * SST + 4]);
            unsigned a0l = __float_as_uint(al[0]);
            unsigned a1l = __float_as_uint(al[8 * SST]);
            unsigned a2l = __float_as_uint(al[4]);
            unsigned a3l = __float_as_uint(al[8 * SST + 4]);
            #pragma unroll
            for (int nt = 0; nt < 8; nt++) {
                int o = (nb + nt) * 8 + gid;
                const float* bh = &s_w_hi[o * SST + kb + tig];
                const float* bl = &s_w_lo[o * SST + kb + tig];
                unsigned b0h = __float_as_uint(bh[0]);
                unsigned b1h = __float_as_uint(bh[4]);
                unsigned b0l = __float_as_uint(bl[0]);
                unsigned b1l = __float_as_uint(bl[4]);
                mma8(c[nt], a0h, a1h, a2h, a3h, b0h, b1h);
                mma8(c[nt], a0h, a1h, a2h, a3h, b0l, b1l);
                mma8(c[nt], a0l, a1l, a2l, a3l, b0h, b1h);
            }
        }
    }
    __syncthreads();   // all compute done before h1T writes race nothing; keep ordering

    // epilogue: C frags -> s_h1T[o][img], bias + relu
    {
        const int m0 = mt * 16 + gid;
        #pragma unroll
        for (int nt = 0; nt < 8; nt++) {
            int o_a = (nb + nt) * 8 + 2 * tig;
            if (o_a < 120) {
                float ba = s_b1[o_a];
                float bb = s_b1[o_a + 1];
                s_h1T[o_a * 64 + m0]           = fmaxf(c[nt][0] + ba, 0.f);
                s_h1T[o_a * 64 + m0 + 8]       = fmaxf(c[nt][2] + ba, 0.f);
                s_h1T[(o_a + 1) * 64 + m0]     = fmaxf(c[nt][1] + bb, 0.f);
                s_h1T[(o_a + 1) * 64 + m0 + 8] = fmaxf(c[nt][3] + bb, 0.f);
            }
        }
    }
    __syncthreads();

    // ---- fc2: [64,120] x [120,84]^T; 8img x 4out tiles; 168 active threads
    if (tid < 168) {
        int oo0 = (tid % 21) * 4;
        int ii0 = (tid / 21) * 8;
        float c2[8][4];
        #pragma unroll
        for (int i = 0; i < 8; i++)
            #pragma unroll
            for (int j = 0; j < 4; j++) c2[i][j] = 0.f;
        #pragma unroll 6
        for (int k = 0; k < 120; k++) {
            float4 wv = *reinterpret_cast<const float4*>(&s_w2T[k * 84 + oo0]);
            float4 a0 = *reinterpret_cast<const float4*>(&s_h1T[k * 64 + ii0]);
            float4 a1 = *reinterpret_cast<const float4*>(&s_h1T[k * 64 + ii0 + 4]);
            c2[0][0] += a0.x * wv.x; c2[0][1] += a0.x * wv.y; c2[0][2] += a0.x * wv.z; c2[0][3] += a0.x * wv.w;
            c2[1][0] += a0.y * wv.x; c2[1][1] += a0.y * wv.y; c2[1][2] += a0.y * wv.z; c2[1][3] += a0.y * wv.w;
            c2[2][0] += a0.z * wv.x; c2[2][1] += a0.z * wv.y; c2[2][2] += a0.z * wv.z; c2[2][3] += a0.z * wv.w;
            c2[3][0] += a0.w * wv.x; c2[3][1] += a0.w * wv.y; c2[3][2] += a0.w * wv.z; c2[3][3] += a0.w * wv.w;
            c2[4][0] += a1.x * wv.x; c2[4][1] += a1.x * wv.y; c2[4][2] += a1.x * wv.z; c2[4][3] += a1.x * wv.w;
            c2[5][0] += a1.y * wv.x; c2[5][1] += a1.y * wv.y; c2[5][2] += a1.y * wv.z; c2[5][3] += a1.y * wv.w;
            c2[6][0] += a1.z * wv.x; c2[6][1] += a1.z * wv.y; c2[6][2] += a1.z * wv.z; c2[6][3] += a1.z * wv.w;
            c2[7][0] += a1.w * wv.x; c2[7][1] += a1.w * wv.y; c2[7][2] += a1.w * wv.z; c2[7][3] += a1.w * wv.w;
        }
        #pragma unroll
        for (int ii = 0; ii < 8; ii++)
            #pragma unroll
            for (int oo = 0; oo < 4; oo++)
                s_h2[(ii0 + ii) * 84 + oo0 + oo] =
                    fmaxf(c2[ii][oo] + s_b2[oo0 + oo], 0.f);
    }
    __syncthreads();

    // ---- fc3: [64,84] x [84,10]^T -> out
    for (int t = tid; t < GFC * 10; t += 256) {
        int o  = t % 10;
        int im = t / 10;
        float a = s_b3[o];
        #pragma unroll
        for (int k = 0; k < 84; k += 4) {
            float4 h = *reinterpret_cast<const float4*>(&s_h2[im * 84 + k]);
            float4 wv = *reinterpret_cast<const float4*>(&s_w3[o * 84 + k]);
            a += h.x * wv.x + h.y * wv.y + h.z * wv.z + h.w * wv.w;
        }
        out[(img0 + im) * 10 + o] = a;
    }
}

extern "C" void kernel_launch(void* const* d_in, const int* in_sizes, int n_in,
                              void* d_out, int out_size)
{
    const float* x   = (const float*)d_in[0];
    const float* w1  = (const float*)d_in[1];
    const float* w2  = (const float*)d_in[2];
    const float* fw1 = (const float*)d_in[3];
    const float* fb1 = (const float*)d_in[4];
    const float* fw2 = (const float*)d_in[5];
    const float* fb2 = (const float*)d_in[6];
    const float* fw3 = (const float*)d_in[7];
    const float* fb3 = (const float*)d_in[8];
    float* out = (float*)d_out;

    const int FC_SMEM = (2 * 64 * SST + 2 * 128 * SST + 120 * 64 + 120 * 84 +
                         840 + 120 + 84 + 12) * (int)sizeof(float);
    cudaFuncSetAttribute(fc_kernel, cudaFuncAttributeMaxDynamicSharedMemorySize,
                         FC_SMEM);

    prep_kernel<<<200, 256>>>(fw1);
    conv_kernel<<<NIMG / 8, 256>>>(x, w1, w2);
    fc_kernel<<<NBLK_FC, 256, FC_SMEM>>>(fb1, fw2, fb2, fw3, fb3, out);
}

// round 12
// speedup vs baseline: 1.1460x; 1.1460x over previous
#include <cuda_runtime.h>
#include <cstddef>

#define NIMG 8192
#define ACT_STRIDE 8256            /* >= 147*56 = 8232; 16B-aligned rows */
#define GFC 56
#define NBLK_FC 147

// Transposed activations: g_actT[k][img], k in [0,400). Tail stays zero.
__device__ __align__(16) float g_actT[(size_t)400 * ACT_STRIDE];

// ---------------------------------------------------------------------------
// Kernel 1: fused conv1->relu->pool1->conv2->relu->pool2 (R9 version, ~floor)
// WARP-PER-IMAGE: 256 threads = 8 warps = 8 images per block.
// ---------------------------------------------------------------------------
__global__ __launch_bounds__(256) void conv_kernel(const float* __restrict__ x,
                                                   const float* __restrict__ w1,
                                                   const float* __restrict__ w2)
{
    __shared__ __align__(16) float s_w1[456];
    __shared__ __align__(16) float s_w2[2400];
    __shared__ __align__(16) float s_A[8][768];
    __shared__ __align__(16) float s_B[8][880];
    __shared__ __align__(16) float s_out[3200];

    const int tid  = threadIdx.x;
    const int wid  = tid >> 5;
    const int lane = tid & 31;
    const int img  = blockIdx.x * 8 + wid;

    for (int i = tid; i < 450; i += 256) s_w1[i] = w1[i];
    for (int i = tid; i < 2400; i += 256) s_w2[i] = w2[i];
    __syncthreads();

    float* A = s_A[wid];
    float* B = s_B[wid];

    const float* xb = x + (size_t)img * 3072;
    for (int i = lane; i < 768; i += 32) {
        int c  = i >> 8;
        int rr = (i >> 4) & 15;
        int cc = i & 15;
        A[i] = xb[c * 1024 + rr * 32 + cc];
    }
    __syncwarp();

    // conv1 + relu: 96 tasks, each 3x3 outputs; sliding-row form
    #pragma unroll
    for (int pass = 0; pass < 3; pass++) {
        int u   = lane + pass * 32;
        int oc  = u >> 4;
        int rem = u & 15;
        int r0  = (rem >> 2) * 3;
        int c0  = (rem & 3) * 3;
        float acc[3][3];
        #pragma unroll
        for (int i = 0; i < 3; i++)
            #pragma unroll
            for (int j = 0; j < 3; j++) acc[i][j] = 0.f;

        for (int c = 0; c < 3; c++) {
            float wreg[25];
            const float* wb = &s_w1[(oc * 3 + c) * 25];
            #pragma unroll
            for (int i = 0; i < 25; i++) wreg[i] = wb[i];
            const float* Ac = &A[c * 256];
            #pragma unroll
            for (int rr = 0; rr < 7; rr++) {
                float p[7];
                const float* pr = &Ac[(r0 + rr) * 16 + c0];
                #pragma unroll
                for (int j = 0; j < 7; j++) p[j] = pr[j];
                #pragma unroll
                for (int orow = 0; orow < 3; orow++) {
                    int uu = rr - orow;
                    if (uu >= 0 && uu < 5) {
                        #pragma unroll
                        for (int v = 0; v < 5; v++) {
                            float w = wreg[uu * 5 + v];
                            #pragma unroll
                            for (int j = 0; j < 3; j++)
                                acc[orow][j] += p[v + j] * w;
                        }
                    }
                }
            }
        }
        #pragma unroll
        for (int orow = 0; orow < 3; orow++)
            #pragma unroll
            for (int j = 0; j < 3; j++)
                B[(oc * 12 + r0 + orow) * 12 + c0 + j] = fmaxf(acc[orow][j], 0.f);
    }
    __syncwarp();

    for (int t = lane; t < 600; t += 32) {
        int oc = t / 100;
        int rr = (t % 100) / 10;
        int cc = t % 10;
        const float* c1 = &B[(oc * 12 + rr) * 12 + cc];
        A[(oc * 10 + rr) * 12 + cc] = fmaxf(fmaxf(c1[0], c1[1]), fmaxf(c1[12], c1[13]));
    }
    __syncwarp();

    // conv2 + relu: 32 tasks = oc(16) x rowhalf(2), weights in regs
    {
        int oc = lane >> 1;
        int r0 = (lane & 1) * 3;
        float acc[3][6];
        #pragma unroll
        for (int i = 0; i < 3; i++)
            #pragma unroll
            for (int j = 0; j < 6; j++) acc[i][j] = 0.f;

        for (int c = 0; c < 6; c++) {
            float wreg[25];
            const float* wb = &s_w2[(oc * 6 + c) * 25];
            #pragma unroll
            for (int i = 0; i < 25; i++) wreg[i] = wb[i];
            #pragma unroll
            for (int rr = 0; rr < 7; rr++) {
                const float* pr = &A[(c * 10 + r0 + rr) * 12];
                float p[10];
                float4 v0 = *reinterpret_cast<const float4*>(&pr[0]);
                float4 v1 = *reinterpret_cast<const float4*>(&pr[4]);
                p[0] = v0.x; p[1] = v0.y; p[2] = v0.z; p[3] = v0.w;
                p[4] = v1.x; p[5] = v1.y; p[6] = v1.z; p[7] = v1.w;
                p[8] = pr[8]; p[9] = pr[9];
                #pragma unroll
                for (int orow = 0; orow < 3; orow++) {
                    int uu = rr - orow;
                    if (uu >= 0 && uu < 5) {
                        #pragma unroll
                        for (int v = 0; v < 5; v++) {
                            float w = wreg[uu * 5 + v];
                            #pragma unroll
                            for (int j = 0; j < 6; j++)
                                acc[orow][j] += p[v + j] * w;
                        }
                    }
                }
            }
        }
        #pragma unroll
        for (int orow = 0; orow < 3; orow++)
            #pragma unroll
            for (int j = 0; j < 6; j++)
                B[(oc * 6 + r0 + orow) * 8 + j] = fmaxf(acc[orow][j], 0.f);
    }
    __syncwarp();

    for (int t = lane; t < 400; t += 32) {
        int oc = t / 25;
        int rr = (t % 25) / 5;
        int cc = t % 5;
        const float* c2 = &B[(oc * 6 + rr) * 8 + cc];
        s_out[t * 8 + wid] = fmaxf(fmaxf(c2[0], c2[1]), fmaxf(c2[8], c2[9]));
    }
    __syncthreads();

    const int img0 = blockIdx.x * 8;
    for (int k = tid; k < 400; k += 256) {
        float4 v0 = *reinterpret_cast<const float4*>(&s_out[k * 8]);
        float4 v1 = *reinterpret_cast<const float4*>(&s_out[k * 8 + 4]);
        float* dst = &g_actT[(size_t)k * ACT_STRIDE + img0];
        *reinterpret_cast<float4*>(dst)     = v0;
        *reinterpret_cast<float4*>(dst + 4) = v1;
    }
}

// ---------------------------------------------------------------------------
// Kernel 2: fused fc1(relu) -> fc2(relu) -> fc3, K-SPLIT by 2.
// 147 blocks x 512 threads; 56 images per block.
// Thread group g = tid>>8 computes a disjoint K-half of the same 8img x 4out
// tiles -> 420 active threads (~14 warps) at 1.5 B/FMA; partials reduced in
// smem. Chunks of 40 double-buffered with register prefetch.
// ---------------------------------------------------------------------------
#define WCH 40
#define NCH 10
#define W1STRIDE 124
#define NPREFW 10   /* ceil(40*120/512) */
#define NPREFA 5    /* ceil(40*56/512)  */

__global__ __launch_bounds__(512) void fc_kernel(const float* __restrict__ fw1,
                                                 const float* __restrict__ fb1,
                                                 const float* __restrict__ fw2,
                                                 const float* __restrict__ fb2,
                                                 const float* __restrict__ fw3,
                                                 const float* __restrict__ fb3,
                                                 float* __restrict__ out)
{
    extern __shared__ __align__(16) float sm[];
    float* s_act  = sm;                           // 2 x [40][56]  = 4480
    float* s_w1c  = s_act + 2 * WCH * GFC;        // 2 x [40][124] = 9920
    float* s_h1T  = s_w1c + 2 * WCH * W1STRIDE;   // [120][56]     = 6720
    float* s_w2T  = s_h1T + 120 * GFC;            // [120][84]     = 10080
    float* s_w3   = s_w2T + 120 * 84;             // 840
    float* s_b1   = s_w3 + 840;                   // 120
    float* s_b2   = s_b1 + 120;                   // 84
    float* s_b3   = s_b2 + 84;                    // 12 (pad)
    float* s_h2   = sm;                           // alias after fc1: [56][84]

    const int tid  = threadIdx.x;
    const int img0 = blockIdx.x * GFC;
    const int g    = tid >> 8;     // K-group 0/1
    const int sub  = tid & 255;

    // stage w2T [k][84] (coalesced LDG), w3, biases
    for (int i = tid; i < 120 * 84; i += 512) {
        int o = i / 120, k = i % 120;
        s_w2T[k * 84 + o] = fw2[i];
    }
    for (int i = tid; i < 840; i += 512) s_w3[i] = fw3[i];
    if (tid < 120) s_b1[tid] = fb1[tid];
    else if (tid < 204) s_b2[tid - 120] = fb2[tid - 120];
    else if (tid < 214) s_b3[tid - 204] = fb3[tid - 204];

    // ---- fc1: [56,400] x [400,120]^T; 8img x 4out tiles; K-split halves
    const int o0 = (sub % 30) * 4;
    const int i0 = (sub / 30) * 8;
    const bool active = (sub < 210);
    const int kofs = g * (WCH / 2);   // 0 or 20 within each chunk
    float acc[8][4];
    #pragma unroll
    for (int i = 0; i < 8; i++)
        #pragma unroll
        for (int j = 0; j < 4; j++) acc[i][j] = 0.f;

    float prw[NPREFW];
    float pra[NPREFA];

    // chunk 0 -> regs -> buf0
    #pragma unroll
    for (int j = 0; j < NPREFW; j++) {
        int i = tid + j * 512;
        if (i < WCH * 120) prw[j] = fw1[(i / WCH) * 400 + (i % WCH)];
    }
    #pragma unroll
    for (int j = 0; j < NPREFA; j++) {
        int i = tid + j * 512;
        if (i < WCH * GFC) pra[j] = g_actT[(size_t)(i / GFC) * ACT_STRIDE + img0 + (i % GFC)];
    }
    #pragma unroll
    for (int j = 0; j < NPREFW; j++) {
        int i = tid + j * 512;
        if (i < WCH * 120) s_w1c[(i % WCH) * W1STRIDE + (i / WCH)] = prw[j];
    }
    #pragma unroll
    for (int j = 0; j < NPREFA; j++) {
        int i = tid + j * 512;
        if (i < WCH * GFC) s_act[i] = pra[j];
    }
    // chunk 1 -> regs
    #pragma unroll
    for (int j = 0; j < NPREFW; j++) {
        int i = tid + j * 512;
        if (i < WCH * 120) prw[j] = fw1[(i / WCH) * 400 + WCH + (i % WCH)];
    }
    #pragma unroll
    for (int j = 0; j < NPREFA; j++) {
        int i = tid + j * 512;
        if (i < WCH * GFC) pra[j] = g_actT[(size_t)(WCH + i / GFC) * ACT_STRIDE + img0 + (i % GFC)];
    }
    __syncthreads();

    for (int ch = 0; ch < NCH; ch++) {
        const float* wbuf = s_w1c + (ch & 1) * (WCH * W1STRIDE) + kofs * W1STRIDE;
        const float* abuf = s_act + (ch & 1) * (WCH * GFC) + kofs * GFC;
        if (active) {
            #pragma unroll 5
            for (int kk = 0; kk < WCH / 2; kk++) {
                float4 w  = *reinterpret_cast<const float4*>(&wbuf[kk * W1STRIDE + o0]);
                float4 a0 = *reinterpret_cast<const float4*>(&abuf[kk * GFC + i0]);
                float4 a1 = *reinterpret_cast<const float4*>(&abuf[kk * GFC + i0 + 4]);
                acc[0][0] += a0.x * w.x; acc[0][1] += a0.x * w.y; acc[0][2] += a0.x * w.z; acc[0][3] += a0.x * w.w;
                acc[1][0] += a0.y * w.x; acc[1][1] += a0.y * w.y; acc[1][2] += a0.y * w.z; acc[1][3] += a0.y * w.w;
                acc[2][0] += a0.z * w.x; acc[2][1] += a0.z * w.y; acc[2][2] += a0.z * w.z; acc[2][3] += a0.z * w.w;
                acc[3][0] += a0.w * w.x; acc[3][1] += a0.w * w.y; acc[3][2] += a0.w * w.z; acc[3][3] += a0.w * w.w;
                acc[4][0] += a1.x * w.x; acc[4][1] += a1.x * w.y; acc[4][2] += a1.x * w.z; acc[4][3] += a1.x * w.w;
                acc[5][0] += a1.y * w.x; acc[5][1] += a1.y * w.y; acc[5][2] += a1.y * w.z; acc[5][3] += a1.y * w.w;
                acc[6][0] += a1.z * w.x; acc[6][1] += a1.z * w.y; acc[6][2] += a1.z * w.z; acc[6][3] += a1.z * w.w;
                acc[7][0] += a1.w * w.x; acc[7][1] += a1.w * w.y; acc[7][2] += a1.w * w.z; acc[7][3] += a1.w * w.w;
            }
        }
        if (ch < NCH - 1) {
            float* nw = s_w1c + ((ch + 1) & 1) * (WCH * W1STRIDE);
            float* na = s_act + ((ch + 1) & 1) * (WCH * GFC);
            #pragma unroll
            for (int j = 0; j < NPREFW; j++) {
                int i = tid + j * 512;
                if (i < WCH * 120) nw[(i % WCH) * W1STRIDE + (i / WCH)] = prw[j];
            }
            #pragma unroll
            for (int j = 0; j < NPREFA; j++) {
                int i = tid + j * 512;
                if (i < WCH * GFC) na[i] = pra[j];
            }
            if (ch < NCH - 2) {
                const int kb = (ch + 2) * WCH;
                #pragma unroll
                for (int j = 0; j < NPREFW; j++) {
                    int i = tid + j * 512;
                    if (i < WCH * 120) prw[j] = fw1[(i / WCH) * 400 + kb + (i % WCH)];
                }
                #pragma unroll
                for (int j = 0; j < NPREFA; j++) {
                    int i = tid + j * 512;
                    if (i < WCH * GFC) pra[j] = g_actT[(size_t)(kb + i / GFC) * ACT_STRIDE + img0 + (i % GFC)];
                }
            }
        }
        __syncthreads();
    }

    // reduce K-halves: g0 stores raw, g1 adds + bias + relu
    if (g == 0 && active) {
        #pragma unroll
        for (int oo = 0; oo < 4; oo++)
            #pragma unroll
            for (int ii = 0; ii < 8; ii++)
                s_h1T[(o0 + oo) * GFC + i0 + ii] = acc[ii][oo];
    }
    __syncthreads();
    if (g == 1 && active) {
        #pragma unroll
        for (int oo = 0; oo < 4; oo++) {
            float b = s_b1[o0 + oo];
            #pragma unroll
            for (int ii = 0; ii < 8; ii++) {
                float* p = &s_h1T[(o0 + oo) * GFC + i0 + ii];
                *p = fmaxf(*p + acc[ii][oo] + b, 0.f);
            }
        }
    }
    __syncthreads();

    // ---- fc2: [56,120] x [120,84]^T; 8img x 4out tiles; K-split 60+60
    {
        const bool act2 = (sub < 147);
        int oo0 = (sub % 21) * 4;
        int ii0 = (sub / 21) * 8;
        float c2[8][4];
        #pragma unroll
        for (int i = 0; i < 8; i++)
            #pragma unroll
            for (int j = 0; j < 4; j++) c2[i][j] = 0.f;
        if (act2) {
            const int k0 = g * 60;
            #pragma unroll 6
            for (int kk = 0; kk < 60; kk++) {
                int k = k0 + kk;
                float4 w  = *reinterpret_cast<const float4*>(&s_w2T[k * 84 + oo0]);
                float4 a0 = *reinterpret_cast<const float4*>(&s_h1T[k * GFC + ii0]);
                float4 a1 = *reinterpret_cast<const float4*>(&s_h1T[k * GFC + ii0 + 4]);
                c2[0][0] += a0.x * w.x; c2[0][1] += a0.x * w.y; c2[0][2] += a0.x * w.z; c2[0][3] += a0.x * w.w;
                c2[1][0] += a0.y * w.x; c2[1][1] += a0.y * w.y; c2[1][2] += a0.y * w.z; c2[1][3] += a0.y * w.w;
                c2[2][0] += a0.z * w.x; c2[2][1] += a0.z * w.y; c2[2][2] += a0.z * w.z; c2[2][3] += a0.z * w.w;
                c2[3][0] += a0.w * w.x; c2[3][1] += a0.w * w.y; c2[3][2] += a0.w * w.z; c2[3][3] += a0.w * w.w;
                c2[4][0] += a1.x * w.x; c2[4][1] += a1.x * w.y; c2[4][2] += a1.x * w.z; c2[4][3] += a1.x * w.w;
                c2[5][0] += a1.y * w.x; c2[5][1] += a1.y * w.y; c2[5][2] += a1.y * w.z; c2[5][3] += a1.y * w.w;
                c2[6][0] += a1.z * w.x; c2[6][1] += a1.z * w.y; c2[6][2] += a1.z * w.z; c2[6][3] += a1.z * w.w;
                c2[7][0] += a1.w * w.x; c2[7][1] += a1.w * w.y; c2[7][2] += a1.w * w.z; c2[7][3] += a1.w * w.w;
            }
        }
        __syncthreads();   // fc1 consumers of s_h1T done; s_h2 alias region free
        if (g == 0 && act2) {
            #pragma unroll
            for (int ii = 0; ii < 8; ii++)
                #pragma unroll
                for (int oo = 0; oo < 4; oo++)
                    s_h2[(ii0 + ii) * 84 + oo0 + oo] = c2[ii][oo];
        }
        __syncthreads();
        if (g == 1 && act2) {
            #pragma unroll
            for (int ii = 0; ii < 8; ii++)
                #pragma unroll
                for (int oo = 0; oo < 4; oo++) {
                    float* p = &s_h2[(ii0 + ii) * 84 + oo0 + oo];
                    *p = fmaxf(*p + c2[ii][oo] + s_b2[oo0 + oo], 0.f);
                }
        }
    }
    __syncthreads();

    // ---- fc3: [56,84] x [84,10]^T -> out (guarded tail)
    for (int t = tid; t < GFC * 10; t += 512) {
        int o  = t % 10;
        int im = t / 10;
        float a = s_b3[o];
        #pragma unroll
        for (int k = 0; k < 84; k += 4) {
            float4 h = *reinterpret_cast<const float4*>(&s_h2[im * 84 + k]);
            float4 w = *reinterpret_cast<const float4*>(&s_w3[o * 84 + k]);
            a += h.x * w.x + h.y * w.y + h.z * w.z + h.w * w.w;
        }
        int gimg = img0 + im;
        if (gimg < NIMG) out[gimg * 10 + o] = a;
    }
}

extern "C" void kernel_launch(void* const* d_in, const int* in_sizes, int n_in,
                              void* d_out, int out_size)
{
    const float* x   = (const float*)d_in[0];
    const float* w1  = (const float*)d_in[1];
    const float* w2  = (const float*)d_in[2];
    const float* fw1 = (const float*)d_in[3];
    const float* fb1 = (const float*)d_in[4];
    const float* fw2 = (const float*)d_in[5];
    const float* fb2 = (const float*)d_in[6];
    const float* fw3 = (const float*)d_in[7];
    const float* fb3 = (const float*)d_in[8];
    float* out = (float*)d_out;

    const int FC_SMEM = (2 * WCH * GFC + 2 * WCH * W1STRIDE + 120 * GFC +
                         120 * 84 + 840 + 120 + 84 + 12) * (int)sizeof(float);
    cudaFuncSetAttribute(fc_kernel, cudaFuncAttributeMaxDynamicSharedMemorySize,
                         FC_SMEM);

    conv_kernel<<<NIMG / 8, 256>>>(x, w1, w2);
    fc_kernel<<<NBLK_FC, 512, FC_SMEM>>>(fw1, fb1, fw2, fb2, fw3, fb3, out);
}

// round 13
// speedup vs baseline: 1.1629x; 1.0147x over previous
#include <cuda_runtime.h>
#include <cstddef>
#include <cstdint>

#define NIMG 8192
#define ACT_STRIDE 8256            /* >= 147*56 = 8232; 16B-aligned rows */
#define GFC 56
#define NBLK_FC 147

// Transposed activations: g_actT[k][img], k in [0,400). Tail stays zero (.bss).
__device__ __align__(16) float g_actT[(size_t)400 * ACT_STRIDE];
// Pre-transposed fc weights (filled by conv blocks 0..7)
__device__ __align__(16) float g_w1T[400 * 120];
__device__ __align__(16) float g_w2T[120 * 84];

__device__ __forceinline__ void cp16(uint32_t dst, const void* src) {
    asm volatile("cp.async.cg.shared.global [%0], [%1], 16;" :: "r"(dst), "l"(src));
}
#define CP_COMMIT() asm volatile("cp.async.commit_group;")
#define CP_WAIT1()  asm volatile("cp.async.wait_group 1;")

// ---------------------------------------------------------------------------
// Kernel 1: fused conv1->relu->pool1->conv2->relu->pool2 (R9 core, ~floor).
// WARP-PER-IMAGE: 256 threads = 8 warps = 8 images per block.
// Blocks 0..7 additionally transpose fc weights into g_w1T/g_w2T (hidden in
// wave-1 slack; conv is ~7 waves deep).
// ---------------------------------------------------------------------------
__global__ __launch_bounds__(256) void conv_kernel(const float* __restrict__ x,
                                                   const float* __restrict__ w1,
                                                   const float* __restrict__ w2,
                                                   const float* __restrict__ fw1,
                                                   const float* __restrict__ fw2)
{
    __shared__ __align__(16) float s_w1[456];
    __shared__ __align__(16) float s_w2[2400];
    __shared__ __align__(16) float s_A[8][768];
    __shared__ __align__(16) float s_B[8][880];
    __shared__ __align__(16) float s_out[3200];

    const int tid  = threadIdx.x;
    const int wid  = tid >> 5;
    const int lane = tid & 31;
    const int img  = blockIdx.x * 8 + wid;

    for (int i = tid; i < 450; i += 256) s_w1[i] = w1[i];
    for (int i = tid; i < 2400; i += 256) s_w2[i] = w2[i];
    __syncthreads();

    float* A = s_A[wid];
    float* B = s_B[wid];

    const float* xb = x + (size_t)img * 3072;
    for (int i = lane; i < 768; i += 32) {
        int c  = i >> 8;
        int rr = (i >> 4) & 15;
        int cc = i & 15;
        A[i] = xb[c * 1024 + rr * 32 + cc];
    }
    __syncwarp();

    // conv1 + relu: 96 tasks, each 3x3 outputs; sliding-row form
    #pragma unroll
    for (int pass = 0; pass < 3; pass++) {
        int u   = lane + pass * 32;
        int oc  = u >> 4;
        int rem = u & 15;
        int r0  = (rem >> 2) * 3;
        int c0  = (rem & 3) * 3;
        float acc[3][3];
        #pragma unroll
        for (int i = 0; i < 3; i++)
            #pragma unroll
            for (int j = 0; j < 3; j++) acc[i][j] = 0.f;

        for (int c = 0; c < 3; c++) {
            float wreg[25];
            const float* wb = &s_w1[(oc * 3 + c) * 25];
            #pragma unroll
            for (int i = 0; i < 25; i++) wreg[i] = wb[i];
            const float* Ac = &A[c * 256];
            #pragma unroll
            for (int rr = 0; rr < 7; rr++) {
                float p[7];
                const float* pr = &Ac[(r0 + rr) * 16 + c0];
                #pragma unroll
                for (int j = 0; j < 7; j++) p[j] = pr[j];
                #pragma unroll
                for (int orow = 0; orow < 3; orow++) {
                    int uu = rr - orow;
                    if (uu >= 0 && uu < 5) {
                        #pragma unroll
                        for (int v = 0; v < 5; v++) {
                            float w = wreg[uu * 5 + v];
                            #pragma unroll
                            for (int j = 0; j < 3; j++)
                                acc[orow][j] += p[v + j] * w;
                        }
                    }
                }
            }
        }
        #pragma unroll
        for (int orow = 0; orow < 3; orow++)
            #pragma unroll
            for (int j = 0; j < 3; j++)
                B[(oc * 12 + r0 + orow) * 12 + c0 + j] = fmaxf(acc[orow][j], 0.f);
    }
    __syncwarp();

    for (int t = lane; t < 600; t += 32) {
        int oc = t / 100;
        int rr = (t % 100) / 10;
        int cc = t % 10;
        const float* c1 = &B[(oc * 12 + rr) * 12 + cc];
        A[(oc * 10 + rr) * 12 + cc] = fmaxf(fmaxf(c1[0], c1[1]), fmaxf(c1[12], c1[13]));
    }
    __syncwarp();

    // conv2 + relu: 32 tasks = oc(16) x rowhalf(2), weights in regs
    {
        int oc = lane >> 1;
        int r0 = (lane & 1) * 3;
        float acc[3][6];
        #pragma unroll
        for (int i = 0; i < 3; i++)
            #pragma unroll
            for (int j = 0; j < 6; j++) acc[i][j] = 0.f;

        for (int c = 0; c < 6; c++) {
            float wreg[25];
            const float* wb = &s_w2[(oc * 6 + c) * 25];
            #pragma unroll
            for (int i = 0; i < 25; i++) wreg[i] = wb[i];
            #pragma unroll
            for (int rr = 0; rr < 7; rr++) {
                const float* pr = &A[(c * 10 + r0 + rr) * 12];
                float p[10];
                float4 v0 = *reinterpret_cast<const float4*>(&pr[0]);
                float4 v1 = *reinterpret_cast<const float4*>(&pr[4]);
                p[0] = v0.x; p[1] = v0.y; p[2] = v0.z; p[3] = v0.w;
                p[4] = v1.x; p[5] = v1.y; p[6] = v1.z; p[7] = v1.w;
                p[8] = pr[8]; p[9] = pr[9];
                #pragma unroll
                for (int orow = 0; orow < 3; orow++) {
                    int uu = rr - orow;
                    if (uu >= 0 && uu < 5) {
                        #pragma unroll
                        for (int v = 0; v < 5; v++) {
                            float w = wreg[uu * 5 + v];
                            #pragma unroll
                            for (int j = 0; j < 6; j++)
                                acc[orow][j] += p[v + j] * w;
                        }
                    }
                }
            }
        }
        #pragma unroll
        for (int orow = 0; orow < 3; orow++)
            #pragma unroll
            for (int j = 0; j < 6; j++)
                B[(oc * 6 + r0 + orow) * 8 + j] = fmaxf(acc[orow][j], 0.f);
    }
    __syncwarp();

    for (int t = lane; t < 400; t += 32) {
        int oc = t / 25;
        int rr = (t % 25) / 5;
        int cc = t % 5;
        const float* c2 = &B[(oc * 6 + rr) * 8 + cc];
        s_out[t * 8 + wid] = fmaxf(fmaxf(c2[0], c2[1]), fmaxf(c2[8], c2[9]));
    }
    __syncthreads();

    const int img0 = blockIdx.x * 8;
    for (int k = tid; k < 400; k += 256) {
        float4 v0 = *reinterpret_cast<const float4*>(&s_out[k * 8]);
        float4 v1 = *reinterpret_cast<const float4*>(&s_out[k * 8 + 4]);
        float* dst = &g_actT[(size_t)k * ACT_STRIDE + img0];
        *reinterpret_cast<float4*>(dst)     = v0;
        *reinterpret_cast<float4*>(dst + 4) = v1;
    }

    // side-job: fc weight transposes (blocks 0..7; hidden in wave-1 slack)
    if (blockIdx.x < 8) {
        const int b = blockIdx.x;
        for (int j = b * 6000 + tid; j < (b + 1) * 6000; j += 256) {
            int o = j % 120, k = j / 120;
            g_w1T[k * 120 + o] = fw1[o * 400 + k];
        }
        for (int j = b * 1260 + tid; j < (b + 1) * 1260; j += 256) {
            int o = j % 84, k = j / 84;
            g_w2T[k * 84 + o] = fw2[o * 120 + k];
        }
    }
}

// ---------------------------------------------------------------------------
// Kernel 2: fused fc1(relu) -> fc2(relu) -> fc3, K-SPLIT by 2, cp.async staged.
// 147 blocks x 512 threads; 56 images per block; ~187 KB smem, 1 block/SM.
// Chunks of 80 (5 chunks), 2-buffer ring, one chunk always in flight.
// ---------------------------------------------------------------------------
#define WCH 80
#define NCH 5
#define AROW 56
#define WROW 124
#define STGF (WCH * AROW + WCH * WROW)   /* 14400 floats per stage */

__global__ __launch_bounds__(512) void fc_kernel(const float* __restrict__ fb1,
                                                 const float* __restrict__ fb2,
                                                 const float* __restrict__ fw3,
                                                 const float* __restrict__ fb3,
                                                 float* __restrict__ out)
{
    extern __shared__ __align__(16) float sm[];
    float* s_stg  = sm;                      // 2 x 14400 = 28800
    float* s_h1T  = sm + 2 * STGF;           // [120][56] = 6720  @28800
    float* s_w2T  = s_h1T + 120 * GFC;       // [120][84] = 10080 @35520
    float* s_w3   = s_w2T + 120 * 84;        // 840               @45600
    float* s_b1   = s_w3 + 840;              // 120
    float* s_b2   = s_b1 + 120;              // 84
    float* s_b3   = s_b2 + 84;               // 12 (pad)
    float* s_h2   = sm;                      // alias after fc1: [56][84]

    const int tid  = threadIdx.x;
    const int img0 = blockIdx.x * GFC;
    const int g    = tid >> 8;     // K-group 0/1
    const int sub  = tid & 255;

    const uint32_t s_base = (uint32_t)__cvta_generic_to_shared(sm);

    // ---- async staging of one chunk (acts: 80x14 segs, w1T: 80x30 segs)
    auto stage = [&](int ch) {
        const int buf = (ch & 1) * STGF;
        const size_t kc = (size_t)ch * WCH;
        for (int j = tid; j < 3520; j += 512) {
            if (j < 1120) {
                int row = j / 14, seg = (j % 14) * 4;
                cp16(s_base + (uint32_t)(buf + row * AROW + seg) * 4,
                     &g_actT[(kc + row) * ACT_STRIDE + img0 + seg]);
            } else {
                int q = j - 1120;
                int row = q / 30, seg = (q % 30) * 4;
                cp16(s_base + (uint32_t)(buf + WCH * AROW + row * WROW + seg) * 4,
                     &g_w1T[(kc + row) * 120 + seg]);
            }
        }
    };

    // prologue: chunk0 | chunk1 + w2T ; biases/w3 plain
    stage(0); CP_COMMIT();
    stage(1);
    for (int j = tid; j < 2520; j += 512)
        cp16(s_base + (uint32_t)(2 * STGF + 6720 + j * 4) * 4, &g_w2T[j * 4]);
    CP_COMMIT();
    for (int i = tid; i < 840; i += 512) s_w3[i] = fw3[i];
    if (tid < 120) s_b1[tid] = fb1[tid];
    else if (tid < 204) s_b2[tid - 120] = fb2[tid - 120];
    else if (tid < 214) s_b3[tid - 204] = fb3[tid - 204];
    CP_WAIT1();
    __syncthreads();

    // ---- fc1: [56,400] x [400,120]^T; 8img x 4out tiles; K-split halves
    const int o0 = (sub % 30) * 4;
    const int i0 = (sub / 30) * 8;
    const bool active = (sub < 210);
    const int kofs = g * (WCH / 2);   // 0 or 40 within chunk
    float acc[8][4];
    #pragma unroll
    for (int i = 0; i < 8; i++)
        #pragma unroll
        for (int j = 0; j < 4; j++) acc[i][j] = 0.f;

    for (int ch = 0; ch < NCH; ch++) {
        const float* abuf = s_stg + (ch & 1) * STGF + kofs * AROW;
        const float* wbuf = s_stg + (ch & 1) * STGF + WCH * AROW + kofs * WROW;
        if (active) {
            #pragma unroll 5
            for (int kk = 0; kk < WCH / 2; kk++) {
                float4 w  = *reinterpret_cast<const float4*>(&wbuf[kk * WROW + o0]);
                float4 a0 = *reinterpret_cast<const float4*>(&abuf[kk * AROW + i0]);
                float4 a1 = *reinterpret_cast<const float4*>(&abuf[kk * AROW + i0 + 4]);
                acc[0][0] += a0.x * w.x; acc[0][1] += a0.x * w.y; acc[0][2] += a0.x * w.z; acc[0][3] += a0.x * w.w;
                acc[1][0] += a0.y * w.x; acc[1][1] += a0.y * w.y; acc[1][2] += a0.y * w.z; acc[1][3] += a0.y * w.w;
                acc[2][0] += a0.z * w.x; acc[2][1] += a0.z * w.y; acc[2][2] += a0.z * w.z; acc[2][3] += a0.z * w.w;
                acc[3][0] += a0.w * w.x; acc[3][1] += a0.w * w.y; acc[3][2] += a0.w * w.z; acc[3][3] += a0.w * w.w;
                acc[4][0] += a1.x * w.x; acc[4][1] += a1.x * w.y; acc[4][2] += a1.x * w.z; acc[4][3] += a1.x * w.w;
                acc[5][0] += a1.y * w.x; acc[5][1] += a1.y * w.y; acc[5][2] += a1.y * w.z; acc[5][3] += a1.y * w.w;
                acc[6][0] += a1.z * w.x; acc[6][1] += a1.z * w.y; acc[6][2] += a1.z * w.z; acc[6][3] += a1.z * w.w;
                acc[7][0] += a1.w * w.x; acc[7][1] += a1.w * w.y; acc[7][2] += a1.w * w.z; acc[7][3] += a1.w * w.w;
            }
        }
        __syncthreads();                 // all done reading this buffer
        if (ch + 2 < NCH) stage(ch + 2); // refill it asynchronously
        CP_COMMIT();
        CP_WAIT1();                      // next chunk's data arrived
        __syncthreads();
    }

    // reduce K-halves: g0 stores raw, g1 adds + bias + relu
    if (g == 0 && active) {
        #pragma unroll
        for (int oo = 0; oo < 4; oo++)
            #pragma unroll
            for (int ii = 0; ii < 8; ii++)
                s_h1T[(o0 + oo) * GFC + i0 + ii] = acc[ii][oo];
    }
    __syncthreads();
    if (g == 1 && active) {
        #pragma unroll
        for (int oo = 0; oo < 4; oo++) {
            float b = s_b1[o0 + oo];
            #pragma unroll
            for (int ii = 0; ii < 8; ii++) {
                float* p = &s_h1T[(o0 + oo) * GFC + i0 + ii];
                *p = fmaxf(*p + acc[ii][oo] + b, 0.f);
            }
        }
    }
    __syncthreads();

    // ---- fc2: [56,120] x [120,84]^T; 8img x 4out tiles; K-split 60+60
    {
        const bool act2 = (sub < 147);
        int oo0 = (sub % 21) * 4;
        int ii0 = (sub / 21) * 8;
        float c2[8][4];
        #pragma unroll
        for (int i = 0; i < 8; i++)
            #pragma unroll
            for (int j = 0; j < 4; j++) c2[i][j] = 0.f;
        if (act2) {
            const int k0 = g * 60;
            #pragma unroll 6
            for (int kk = 0; kk < 60; kk++) {
                int k = k0 + kk;
                float4 w  = *reinterpret_cast<const float4*>(&s_w2T[k * 84 + oo0]);
                float4 a0 = *reinterpret_cast<const float4*>(&s_h1T[k * GFC + ii0]);
                float4 a1 = *reinterpret_cast<const float4*>(&s_h1T[k * GFC + ii0 + 4]);
                c2[0][0] += a0.x * w.x; c2[0][1] += a0.x * w.y; c2[0][2] += a0.x * w.z; c2[0][3] += a0.x * w.w;
                c2[1][0] += a0.y * w.x; c2[1][1] += a0.y * w.y; c2[1][2] += a0.y * w.z; c2[1][3] += a0.y * w.w;
                c2[2][0] += a0.z * w.x; c2[2][1] += a0.z * w.y; c2[2][2] += a0.z * w.z; c2[2][3] += a0.z * w.w;
                c2[3][0] += a0.w * w.x; c2[3][1] += a0.w * w.y; c2[3][2] += a0.w * w.z; c2[3][3] += a0.w * w.w;
                c2[4][0] += a1.x * w.x; c2[4][1] += a1.x * w.y; c2[4][2] += a1.x * w.z; c2[4][3] += a1.x * w.w;
                c2[5][0] += a1.y * w.x; c2[5][1] += a1.y * w.y; c2[5][2] += a1.y * w.z; c2[5][3] += a1.y * w.w;
                c2[6][0] += a1.z * w.x; c2[6][1] += a1.z * w.y; c2[6][2] += a1.z * w.z; c2[6][3] += a1.z * w.w;
                c2[7][0] += a1.w * w.x; c2[7][1] += a1.w * w.y; c2[7][2] += a1.w * w.z; c2[7][3] += a1.w * w.w;
            }
        }
        __syncthreads();   // staging buffers free -> s_h2 alias safe
        if (g == 0 && act2) {
            #pragma unroll
            for (int ii = 0; ii < 8; ii++)
                #pragma unroll
                for (int oo = 0; oo < 4; oo++)
                    s_h2[(ii0 + ii) * 84 + oo0 + oo] = c2[ii][oo];
        }
        __syncthreads();
        if (g == 1 && act2) {
            #pragma unroll
            for (int ii = 0; ii < 8; ii++)
                #pragma unroll
                for (int oo = 0; oo < 4; oo++) {
                    float* p = &s_h2[(ii0 + ii) * 84 + oo0 + oo];
                    *p = fmaxf(*p + c2[ii][oo] + s_b2[oo0 + oo], 0.f);
                }
        }
    }
    __syncthreads();

    // ---- fc3: [56,84] x [84,10]^T -> out (guarded tail)
    for (int t = tid; t < GFC * 10; t += 512) {
        int o  = t % 10;
        int im = t / 10;
        float a = s_b3[o];
        #pragma unroll
        for (int k = 0; k < 84; k += 4) {
            float4 h = *reinterpret_cast<const float4*>(&s_h2[im * 84 + k]);
            float4 w = *reinterpret_cast<const float4*>(&s_w3[o * 84 + k]);
            a += h.x * w.x + h.y * w.y + h.z * w.z + h.w * w.w;
        }
        int gimg = img0 + im;
        if (gimg < NIMG) out[gimg * 10 + o] = a;
    }
}

extern "C" void kernel_launch(void* const* d_in, const int* in_sizes, int n_in,
                              void* d_out, int out_size)
{
    const float* x   = (const float*)d_in[0];
    const float* w1  = (const float*)d_in[1];
    const float* w2  = (const float*)d_in[2];
    const float* fw1 = (const float*)d_in[3];
    const float* fb1 = (const float*)d_in[4];
    const float* fw2 = (const float*)d_in[5];
    const float* fb2 = (const float*)d_in[6];
    const float* fw3 = (const float*)d_in[7];
    const float* fb3 = (const float*)d_in[8];
    float* out = (float*)d_out;

    const int FC_SMEM = (2 * STGF + 120 * GFC + 120 * 84 + 840 + 120 + 84 + 12) *
                        (int)sizeof(float);
    cudaFuncSetAttribute(fc_kernel, cudaFuncAttributeMaxDynamicSharedMemorySize,
                         FC_SMEM);

    conv_kernel<<<NIMG / 8, 256>>>(x, w1, w2, fw1, fw2);
    fc_kernel<<<NBLK_FC, 512, FC_SMEM>>>(fb1, fb2, fw3, fb3, out);
}